// round 1
// baseline (speedup 1.0000x reference)
#include <cuda_runtime.h>
#include <math.h>

// Problem constants (fixed shapes: z = (16, 128, 64, 64) fp32, codebook = (1024, 128) fp32)
#define CDIM    128
#define KCODES  1024
#define HWDIM   4096          // 64*64 pixels per batch image
#define NPIXMAX 65536         // 16 * 4096
#define QBLOCKS_MAX 32768     // (NPIXMAX*CDIM)/256

// ---- scratch (no allocations allowed; __device__ globals are the sanctioned path) ----
__device__ float  g_zz[NPIXMAX];         // per-pixel sum(z^2), sequential fp32 (matches XLA reduce)
__device__ float  g_ee[KCODES];          // per-code sum(e^2), sequential fp32
__device__ int    g_idx[NPIXMAX];        // argmin indices
__device__ int    g_counts[KCODES];      // code histogram
__device__ double g_partials[QBLOCKS_MAX]; // deterministic per-block loss partial sums
__device__ float  g_idx_scratch[NPIXMAX];  // fallback index sink if out buffer too small

// ------------------------------------------------------------------
// zero the histogram (must run each graph replay)
// ------------------------------------------------------------------
__global__ void zero_counts_kernel() {
    int i = blockIdx.x * blockDim.x + threadIdx.x;
    if (i < KCODES) g_counts[i] = 0;
}

// ------------------------------------------------------------------
// zz[n] = sum_c fl(z[b,c,hw]^2), strictly sequential fp32 adds
// (replicates jnp.sum(z_flat*z_flat, axis=1) rounding behavior)
// ------------------------------------------------------------------
__global__ void zz_kernel(const float* __restrict__ z, int npix) {
    int n = blockIdx.x * blockDim.x + threadIdx.x;
    if (n >= npix) return;
    int b  = n / HWDIM;
    int hw = n - b * HWDIM;
    const float* p = z + ((size_t)b * CDIM) * HWDIM + hw;
    float s = 0.0f;
#pragma unroll
    for (int c = 0; c < CDIM; c++) {
        float v = p[(size_t)c * HWDIM];
        s = __fadd_rn(s, __fmul_rn(v, v));   // no FMA, no reassociation
    }
    g_zz[n] = s;
}

// ------------------------------------------------------------------
// ee[k] = sum_c fl(e[k,c]^2), strictly sequential fp32
// ------------------------------------------------------------------
__global__ void ee_kernel(const float* __restrict__ cb) {
    int k = blockIdx.x * blockDim.x + threadIdx.x;
    if (k >= KCODES) return;
    const float* p = cb + (size_t)k * CDIM;
    float s = 0.0f;
#pragma unroll
    for (int c = 0; c < CDIM; c++) {
        float v = p[c];
        s = __fadd_rn(s, __fmul_rn(v, v));
    }
    g_ee[k] = s;
}

// ------------------------------------------------------------------
// argmin kernel: each block = 64-pixel tile x all 1024 codes.
// 256 threads; thread (tp = tid>>5, lane = tid&31) owns 8 pixels x 4
// consecutive codes per 128-code tile. Dot accumulated as a sequential
// fp32 FMA chain over c (ascending), matching Eigen's gebp accumulation.
// d2 = fl(fl(zz - fl(2*dot)) + ee); first-minimum tie-break (lowest k).
// ------------------------------------------------------------------
__global__ void __launch_bounds__(256) argmin_kernel(
        const float* __restrict__ z, const float* __restrict__ cb) {
    __shared__ float zs[8][64];    // [c-chunk][pixel]
    __shared__ float es[8][132];   // [c-chunk][code], padded to kill write conflicts

    const int tid  = threadIdx.x;
    const int lane = tid & 31;
    const int tp   = tid >> 5;

    const int n0  = blockIdx.x * 64;       // tile of 64 pixels (never straddles b: 4096 % 64 == 0)
    const int b   = n0 / HWDIM;
    const int hw0 = n0 - b * HWDIM;
    const float* zbase = z + ((size_t)b * CDIM) * HWDIM + hw0;

    float zzr[8];
#pragma unroll
    for (int pp = 0; pp < 8; pp++) zzr[pp] = g_zz[n0 + tp * 8 + pp];

    float bestv[8];
    int   besti[8];
#pragma unroll
    for (int pp = 0; pp < 8; pp++) { bestv[pp] = 3.4e38f; besti[pp] = 0x7fffffff; }

    for (int kt = 0; kt < KCODES / 128; kt++) {
        float acc[8][4];
#pragma unroll
        for (int pp = 0; pp < 8; pp++)
#pragma unroll
            for (int j = 0; j < 4; j++) acc[pp][j] = 0.0f;

        for (int c0 = 0; c0 < CDIM; c0 += 8) {
            __syncthreads();   // protect previous chunk's reads
            // load z tile: 8 c-rows x 64 pixels (coalesced 64-float rows)
#pragma unroll
            for (int r = 0; r < 2; r++) {
                int e  = tid + r * 256;
                int ci = e >> 6;
                int p  = e & 63;
                zs[ci][p] = zbase[(size_t)(c0 + ci) * HWDIM + p];
            }
            // load codebook tile transposed: 128 codes x 8 c (float4 per half-row)
            {
                int kk = tid >> 1;
                int h  = (tid & 1) * 4;
                const float4 v = *(const float4*)(cb + ((size_t)(kt * 128 + kk)) * CDIM + c0 + h);
                es[h + 0][kk] = v.x;
                es[h + 1][kk] = v.y;
                es[h + 2][kk] = v.z;
                es[h + 3][kk] = v.w;
            }
            __syncthreads();
#pragma unroll
            for (int ci = 0; ci < 8; ci++) {
                float4 za = *(const float4*)&zs[ci][tp * 8];       // broadcast within warp
                float4 zc = *(const float4*)&zs[ci][tp * 8 + 4];
                float4 er = *(const float4*)&es[ci][lane * 4];     // conflict-free
                float zr[8] = {za.x, za.y, za.z, za.w, zc.x, zc.y, zc.z, zc.w};
                float ev[4] = {er.x, er.y, er.z, er.w};
#pragma unroll
                for (int pp = 0; pp < 8; pp++)
#pragma unroll
                    for (int j = 0; j < 4; j++)
                        acc[pp][j] = fmaf(zr[pp], ev[j], acc[pp][j]);  // sequential FMA chain over c
            }
        }
        // scores for this 128-code tile; per-thread scan order is ascending k
#pragma unroll
        for (int j = 0; j < 4; j++) {
            int k = kt * 128 + lane * 4 + j;
            float ee = g_ee[k];
#pragma unroll
            for (int pp = 0; pp < 8; pp++) {
                float d2 = __fadd_rn(__fsub_rn(zzr[pp], __fmul_rn(2.0f, acc[pp][j])), ee);
                if (d2 < bestv[pp]) { bestv[pp] = d2; besti[pp] = k; }  // strict < => first min
            }
        }
    }
    // warp reduction; tie -> smaller index (matches jnp.argmin first-occurrence)
#pragma unroll
    for (int off = 16; off > 0; off >>= 1) {
#pragma unroll
        for (int pp = 0; pp < 8; pp++) {
            float ov = __shfl_down_sync(0xffffffffu, bestv[pp], off);
            int   oi = __shfl_down_sync(0xffffffffu, besti[pp], off);
            if (ov < bestv[pp] || (ov == bestv[pp] && oi < besti[pp])) {
                bestv[pp] = ov; besti[pp] = oi;
            }
        }
    }
    if (lane == 0) {
#pragma unroll
        for (int pp = 0; pp < 8; pp++) g_idx[n0 + tp * 8 + pp] = besti[pp];
    }
}

// ------------------------------------------------------------------
// gather + straight-through output + deterministic per-block loss partials
// out[i] = fl(z + fl(q - z));  partial += (double)fl((z-q)^2)
// ------------------------------------------------------------------
__global__ void __launch_bounds__(256) quant_kernel(
        const float* __restrict__ z, const float* __restrict__ cb,
        float* __restrict__ outq, int total) {
    __shared__ double sh[8];
    int i = blockIdx.x * 256 + threadIdx.x;
    double sq = 0.0;
    if (i < total) {
        int hw = i & (HWDIM - 1);
        int c  = (i >> 12) & (CDIM - 1);
        int b  = i >> 19;
        int n  = b * HWDIM + hw;
        int k  = g_idx[n];
        float zv = z[i];
        float q  = cb[(size_t)k * CDIM + c];
        outq[i]  = __fadd_rn(zv, __fsub_rn(q, zv));   // exact STE rounding replication
        float d  = __fsub_rn(zv, q);
        sq = (double)__fmul_rn(d, d);
    }
#pragma unroll
    for (int off = 16; off > 0; off >>= 1)
        sq += __shfl_down_sync(0xffffffffu, sq, off);
    int warp = threadIdx.x >> 5;
    if ((threadIdx.x & 31) == 0) sh[warp] = sq;
    __syncthreads();
    if (threadIdx.x == 0) {
        double s = 0.0;
        for (int w = 0; w < 8; w++) s += sh[w];   // fixed order -> deterministic
        g_partials[blockIdx.x] = s;
    }
}

// ------------------------------------------------------------------
// histogram (int atomics = order-independent/deterministic) + index->float output
// ------------------------------------------------------------------
__global__ void hist_kernel(float* __restrict__ idx_out, int npix, int write_out) {
    __shared__ int h[KCODES];
    float* dst = write_out ? idx_out : g_idx_scratch;
    for (int i = threadIdx.x; i < KCODES; i += blockDim.x) h[i] = 0;
    __syncthreads();
    for (int n = blockIdx.x * blockDim.x + threadIdx.x; n < npix;
         n += gridDim.x * blockDim.x) {
        int k = g_idx[n];
        atomicAdd(&h[k], 1);
        dst[n] = (float)k;
    }
    __syncthreads();
    for (int i = threadIdx.x; i < KCODES; i += blockDim.x)
        if (h[i]) atomicAdd(&g_counts[i], h[i]);
}

// ------------------------------------------------------------------
// final deterministic reduction + scalars:
// vq_loss = fl(m + fl(0.25*m)) with m = (float)(sum/total)
// perplexity = exp(-sum p*log(p+1e-10))
// ------------------------------------------------------------------
__global__ void finalize_kernel(float* __restrict__ out2, int nblocks,
                                double inv_total, int npix) {
    __shared__ double sh[256];
    double s = 0.0;
    for (int i = threadIdx.x; i < nblocks; i += 256) s += g_partials[i];
    sh[threadIdx.x] = s;
    __syncthreads();
    for (int st = 128; st > 0; st >>= 1) {
        if (threadIdx.x < st) sh[threadIdx.x] += sh[threadIdx.x + st];
        __syncthreads();
    }
    if (threadIdx.x == 0) {
        double mse = sh[0] * inv_total;
        float m  = (float)mse;
        float vq = __fadd_rn(m, __fmul_rn(0.25f, m));
        double H = 0.0;
        for (int k = 0; k < KCODES; k++) {
            double p = (double)g_counts[k] / (double)npix;
            H -= p * log(p + 1e-10);
        }
        out2[0] = vq;
        out2[1] = (float)exp(H);
    }
}

// ------------------------------------------------------------------
// launch: all default-stream kernel launches, graph-capturable,
// allocation-free. Assumed output layout (all float32, concatenated):
// [quantized (total) | indices (npix) | vq_loss (1) | perplexity (1)]
// Guarded by out_size so a different layout can't fault.
// ------------------------------------------------------------------
extern "C" void kernel_launch(void* const* d_in, const int* in_sizes, int n_in,
                              void* d_out, int out_size) {
    const float* z  = (const float*)d_in[0];
    const float* cb = (const float*)d_in[1];
    float* out = (float*)d_out;

    int total   = in_sizes[0];          // 8388608 z elements
    int npix    = total / CDIM;         // 65536
    int qblocks = (total + 255) / 256;  // 32768

    zero_counts_kernel<<<(KCODES + 255) / 256, 256>>>();
    zz_kernel<<<(npix + 255) / 256, 256>>>(z, npix);
    ee_kernel<<<(KCODES + 255) / 256, 256>>>(cb);
    argmin_kernel<<<npix / 64, 256>>>(z, cb);
    quant_kernel<<<qblocks, 256>>>(z, cb, out, total);

    int write_idx = (out_size >= total + npix) ? 1 : 0;
    hist_kernel<<<64, 256>>>(out + total, npix, write_idx);

    if (out_size >= total + npix + 2) {
        finalize_kernel<<<1, 256>>>(out + total + npix, qblocks,
                                    1.0 / (double)total, npix);
    }
    (void)n_in;
}

// round 2
// speedup vs baseline: 3.9588x; 3.9588x over previous
#include <cuda_runtime.h>
#include <math.h>

// Problem constants (fixed shapes: z = (16, 128, 64, 64) fp32, codebook = (1024, 128) fp32)
#define CDIM    128
#define KCODES  1024
#define HWDIM   4096          // 64*64 pixels per batch image
#define NPIXMAX 65536         // 16 * 4096
#define PBLOCKS 1024          // quant partial blocks

// ---- scratch (no allocations allowed; __device__ globals are the sanctioned path) ----
__device__ float  g_zz[NPIXMAX];         // per-pixel sum(z^2), sequential fp32
__device__ float  g_ee[KCODES];          // per-code sum(e^2), sequential fp32
__device__ int    g_idx[NPIXMAX];        // argmin indices
__device__ int    g_counts[KCODES];      // code histogram
__device__ double g_partials[PBLOCKS];   // deterministic per-block loss partials
__device__ float  g_idx_scratch[NPIXMAX];// fallback index sink if out buffer too small

// ---- packed fp32x2 helpers (lanewise IEEE fp32 => numerics identical to scalar) ----
__device__ __forceinline__ unsigned long long dup_f32(float x) {
    unsigned long long r;
    asm("mov.b64 %0, {%1, %1};" : "=l"(r) : "f"(x));
    return r;
}
__device__ __forceinline__ void fma_f32x2(unsigned long long& d,
                                          unsigned long long a,
                                          unsigned long long b) {
    asm("fma.rn.f32x2 %0, %1, %2, %3;" : "=l"(d) : "l"(a), "l"(b), "l"(d));
}
__device__ __forceinline__ void unpack_f32x2(float& lo, float& hi, unsigned long long v) {
    asm("mov.b64 {%0, %1}, %2;" : "=f"(lo), "=f"(hi) : "l"(v));
}

// ------------------------------------------------------------------
__global__ void zero_counts_kernel() {
    int i = blockIdx.x * blockDim.x + threadIdx.x;
    if (i < KCODES) g_counts[i] = 0;
}

// ------------------------------------------------------------------
// zz[n] = sum_c fl(z[b,c,hw]^2), strictly sequential fp32 adds
// ------------------------------------------------------------------
__global__ void zz_kernel(const float* __restrict__ z, int npix) {
    int n = blockIdx.x * blockDim.x + threadIdx.x;
    if (n >= npix) return;
    int b  = n / HWDIM;
    int hw = n - b * HWDIM;
    const float* p = z + ((size_t)b * CDIM) * HWDIM + hw;
    float s = 0.0f;
#pragma unroll
    for (int c = 0; c < CDIM; c++) {
        float v = p[(size_t)c * HWDIM];
        s = __fadd_rn(s, __fmul_rn(v, v));   // no FMA, no reassociation
    }
    g_zz[n] = s;
}

// ------------------------------------------------------------------
__global__ void ee_kernel(const float* __restrict__ cb) {
    int k = blockIdx.x * blockDim.x + threadIdx.x;
    if (k >= KCODES) return;
    const float* p = cb + (size_t)k * CDIM;
    float s = 0.0f;
#pragma unroll
    for (int c = 0; c < CDIM; c++) {
        float v = p[c];
        s = __fadd_rn(s, __fmul_rn(v, v));
    }
    g_ee[k] = s;
}

// ------------------------------------------------------------------
// argmin kernel: block = 64-pixel tile x all 1024 codes; 256 threads.
// Thread (tp = warp, lane) owns 8 pixels x 4 consecutive codes per
// 128-code tile. Inner product uses packed fma.rn.f32x2 with PIXEL
// PAIRS in the two fp32 lanes -> 2x fma-pipe throughput, per-lane
// accumulation chain identical to scalar (same rounding, same order).
// d2 = fl(fl(zz - fl(2*dot)) + ee); first-minimum tie-break.
// ------------------------------------------------------------------
__global__ void __launch_bounds__(256) argmin_kernel(
        const float* __restrict__ z, const float* __restrict__ cb) {
    __shared__ __align__(16) float zs[8][64];    // [c-chunk][pixel]
    __shared__ __align__(16) float es[8][132];   // [c-chunk][code], padded

    const int tid  = threadIdx.x;
    const int lane = tid & 31;
    const int tp   = tid >> 5;

    const int n0  = blockIdx.x * 64;       // 4096 % 64 == 0 -> tile never straddles b
    const int b   = n0 / HWDIM;
    const int hw0 = n0 - b * HWDIM;
    const float* zbase = z + ((size_t)b * CDIM) * HWDIM + hw0;

    float zzr[8];
#pragma unroll
    for (int pp = 0; pp < 8; pp++) zzr[pp] = g_zz[n0 + tp * 8 + pp];

    float bestv[8];
    int   besti[8];
#pragma unroll
    for (int pp = 0; pp < 8; pp++) { bestv[pp] = 3.4e38f; besti[pp] = 0x7fffffff; }

    for (int kt = 0; kt < KCODES / 128; kt++) {
        // acc[pq][j]: pq = pixel pair (lanes: lo = pixel 2pq, hi = pixel 2pq+1)
        unsigned long long acc[4][4];
#pragma unroll
        for (int pq = 0; pq < 4; pq++)
#pragma unroll
            for (int j = 0; j < 4; j++) acc[pq][j] = 0ull;

        for (int c0 = 0; c0 < CDIM; c0 += 8) {
            __syncthreads();   // protect previous chunk's reads
            // z tile: 8 c-rows x 64 pixels (coalesced 64-float rows)
#pragma unroll
            for (int r = 0; r < 2; r++) {
                int e  = tid + r * 256;
                int ci = e >> 6;
                int p  = e & 63;
                zs[ci][p] = zbase[(size_t)(c0 + ci) * HWDIM + p];
            }
            // codebook tile transposed: 128 codes x 8 c
            {
                int kk = tid >> 1;
                int h  = (tid & 1) * 4;
                const float4 v = *(const float4*)(cb + ((size_t)(kt * 128 + kk)) * CDIM + c0 + h);
                es[h + 0][kk] = v.x;
                es[h + 1][kk] = v.y;
                es[h + 2][kk] = v.z;
                es[h + 3][kk] = v.w;
            }
            __syncthreads();
#pragma unroll
            for (int ci = 0; ci < 8; ci++) {
                // 4 pixel pairs, adjacent floats -> direct 64-bit shared loads (broadcast)
                const unsigned long long* zp =
                    (const unsigned long long*)&zs[ci][tp * 8];
                unsigned long long zp0 = zp[0], zp1 = zp[1], zp2 = zp[2], zp3 = zp[3];
                float4 er = *(const float4*)&es[ci][lane * 4];     // conflict-free
                unsigned long long e0 = dup_f32(er.x);
                unsigned long long e1 = dup_f32(er.y);
                unsigned long long e2 = dup_f32(er.z);
                unsigned long long e3 = dup_f32(er.w);
                fma_f32x2(acc[0][0], zp0, e0); fma_f32x2(acc[0][1], zp0, e1);
                fma_f32x2(acc[0][2], zp0, e2); fma_f32x2(acc[0][3], zp0, e3);
                fma_f32x2(acc[1][0], zp1, e0); fma_f32x2(acc[1][1], zp1, e1);
                fma_f32x2(acc[1][2], zp1, e2); fma_f32x2(acc[1][3], zp1, e3);
                fma_f32x2(acc[2][0], zp2, e0); fma_f32x2(acc[2][1], zp2, e1);
                fma_f32x2(acc[2][2], zp2, e2); fma_f32x2(acc[2][3], zp2, e3);
                fma_f32x2(acc[3][0], zp3, e0); fma_f32x2(acc[3][1], zp3, e1);
                fma_f32x2(acc[3][2], zp3, e2); fma_f32x2(acc[3][3], zp3, e3);
            }
        }
        // scores; per-pixel scan order is ascending k (first-min tie-break)
#pragma unroll
        for (int j = 0; j < 4; j++) {
            int k = kt * 128 + lane * 4 + j;
            float ee = g_ee[k];
#pragma unroll
            for (int pq = 0; pq < 4; pq++) {
                float dlo, dhi;
                unpack_f32x2(dlo, dhi, acc[pq][j]);
                float d2lo = __fadd_rn(__fsub_rn(zzr[2 * pq + 0], __fmul_rn(2.0f, dlo)), ee);
                float d2hi = __fadd_rn(__fsub_rn(zzr[2 * pq + 1], __fmul_rn(2.0f, dhi)), ee);
                if (d2lo < bestv[2 * pq + 0]) { bestv[2 * pq + 0] = d2lo; besti[2 * pq + 0] = k; }
                if (d2hi < bestv[2 * pq + 1]) { bestv[2 * pq + 1] = d2hi; besti[2 * pq + 1] = k; }
            }
        }
    }
    // warp reduction; tie -> smaller index (jnp.argmin first-occurrence)
#pragma unroll
    for (int off = 16; off > 0; off >>= 1) {
#pragma unroll
        for (int pp = 0; pp < 8; pp++) {
            float ov = __shfl_down_sync(0xffffffffu, bestv[pp], off);
            int   oi = __shfl_down_sync(0xffffffffu, besti[pp], off);
            if (ov < bestv[pp] || (ov == bestv[pp] && oi < besti[pp])) {
                bestv[pp] = ov; besti[pp] = oi;
            }
        }
    }
    if (lane == 0) {
#pragma unroll
        for (int pp = 0; pp < 8; pp++) g_idx[n0 + tp * 8 + pp] = besti[pp];
    }
}

// ------------------------------------------------------------------
// gather + straight-through output + deterministic loss partials.
// Grid-stride with PBLOCKS big blocks (kills the 221-wave tiny-block
// overhead of round 1). float4 I/O; per-thread double accumulation in
// a fixed traversal order -> deterministic across graph replays.
// ------------------------------------------------------------------
__global__ void __launch_bounds__(256) quant_kernel(
        const float* __restrict__ z, const float* __restrict__ cb,
        float* __restrict__ outq, int total) {
    __shared__ double sh[8];
    double sq = 0.0;
    const int stride = gridDim.x * blockDim.x * 4;
    int total4 = total & ~3;
    for (int base = (blockIdx.x * blockDim.x + threadIdx.x) * 4; base < total4;
         base += stride) {
        float4 zv = *(const float4*)(z + base);
        int hw = base & (HWDIM - 1);            // 4 elems stay in one (b,c) row
        int c  = (base >> 12) & (CDIM - 1);
        int b  = base >> 19;
        int n  = b * HWDIM + hw;
        float q0 = cb[(size_t)g_idx[n + 0] * CDIM + c];
        float q1 = cb[(size_t)g_idx[n + 1] * CDIM + c];
        float q2 = cb[(size_t)g_idx[n + 2] * CDIM + c];
        float q3 = cb[(size_t)g_idx[n + 3] * CDIM + c];
        float4 o;
        o.x = __fadd_rn(zv.x, __fsub_rn(q0, zv.x));   // exact STE rounding
        o.y = __fadd_rn(zv.y, __fsub_rn(q1, zv.y));
        o.z = __fadd_rn(zv.z, __fsub_rn(q2, zv.z));
        o.w = __fadd_rn(zv.w, __fsub_rn(q3, zv.w));
        *(float4*)(outq + base) = o;
        float d0 = __fsub_rn(zv.x, q0), d1 = __fsub_rn(zv.y, q1);
        float d2 = __fsub_rn(zv.z, q2), d3 = __fsub_rn(zv.w, q3);
        sq += (double)__fmul_rn(d0, d0);
        sq += (double)__fmul_rn(d1, d1);
        sq += (double)__fmul_rn(d2, d2);
        sq += (double)__fmul_rn(d3, d3);
    }
    // scalar tail (only if total % 4 != 0; not hit for this shape)
    for (int i = total4 + blockIdx.x * blockDim.x + threadIdx.x; i < total;
         i += gridDim.x * blockDim.x) {
        int hw = i & (HWDIM - 1);
        int c  = (i >> 12) & (CDIM - 1);
        int b  = i >> 19;
        int k  = g_idx[b * HWDIM + hw];
        float zv = z[i];
        float q  = cb[(size_t)k * CDIM + c];
        outq[i]  = __fadd_rn(zv, __fsub_rn(q, zv));
        float d  = __fsub_rn(zv, q);
        sq += (double)__fmul_rn(d, d);
    }
#pragma unroll
    for (int off = 16; off > 0; off >>= 1)
        sq += __shfl_down_sync(0xffffffffu, sq, off);
    int warp = threadIdx.x >> 5;
    if ((threadIdx.x & 31) == 0) sh[warp] = sq;
    __syncthreads();
    if (threadIdx.x == 0) {
        double s = 0.0;
        for (int w = 0; w < 8; w++) s += sh[w];   // fixed order -> deterministic
        g_partials[blockIdx.x] = s;
    }
}

// ------------------------------------------------------------------
// histogram (int atomics = order-independent) + index->float output
// ------------------------------------------------------------------
__global__ void hist_kernel(float* __restrict__ idx_out, int npix, int write_out) {
    __shared__ int h[KCODES];
    float* dst = write_out ? idx_out : g_idx_scratch;
    for (int i = threadIdx.x; i < KCODES; i += blockDim.x) h[i] = 0;
    __syncthreads();
    for (int n = blockIdx.x * blockDim.x + threadIdx.x; n < npix;
         n += gridDim.x * blockDim.x) {
        int k = g_idx[n];
        atomicAdd(&h[k], 1);
        dst[n] = (float)k;
    }
    __syncthreads();
    for (int i = threadIdx.x; i < KCODES; i += blockDim.x)
        if (h[i]) atomicAdd(&g_counts[i], h[i]);
}

// ------------------------------------------------------------------
// finalize: fully parallel now (round-1 version ran 1024 serial
// double-divide + double-log on ONE thread => ~1 ms).
// vq_loss = fl(m + fl(0.25*m)), m = (float)(sum/total)
// perplexity = exp(-sum p*log(p+1e-10)), entropy parallel over codes.
// ------------------------------------------------------------------
__global__ void finalize_kernel(float* __restrict__ out2, int nblocks,
                                double inv_total, int npix) {
    __shared__ double sh[256];
    __shared__ double sh2[256];
    double s = 0.0;
    for (int i = threadIdx.x; i < nblocks; i += 256) s += g_partials[i];
    double h = 0.0;
    double inv_n = 1.0 / (double)npix;
    for (int k = threadIdx.x; k < KCODES; k += 256) {
        double p = (double)g_counts[k] * inv_n;
        h -= p * log(p + 1e-10);
    }
    sh[threadIdx.x]  = s;
    sh2[threadIdx.x] = h;
    __syncthreads();
    for (int st = 128; st > 0; st >>= 1) {
        if (threadIdx.x < st) {
            sh[threadIdx.x]  += sh[threadIdx.x + st];
            sh2[threadIdx.x] += sh2[threadIdx.x + st];
        }
        __syncthreads();
    }
    if (threadIdx.x == 0) {
        double mse = sh[0] * inv_total;
        float m  = (float)mse;
        out2[0] = __fadd_rn(m, __fmul_rn(0.25f, m));
        out2[1] = (float)exp(sh2[0]);
    }
}

// ------------------------------------------------------------------
// Output layout (all float32): [quantized (total) | indices (npix) |
// vq_loss (1) | perplexity (1)] — guarded by out_size.
// ------------------------------------------------------------------
extern "C" void kernel_launch(void* const* d_in, const int* in_sizes, int n_in,
                              void* d_out, int out_size) {
    const float* z  = (const float*)d_in[0];
    const float* cb = (const float*)d_in[1];
    float* out = (float*)d_out;

    int total = in_sizes[0];          // 8388608
    int npix  = total / CDIM;         // 65536

    zero_counts_kernel<<<(KCODES + 255) / 256, 256>>>();
    zz_kernel<<<(npix + 255) / 256, 256>>>(z, npix);
    ee_kernel<<<(KCODES + 255) / 256, 256>>>(cb);
    argmin_kernel<<<npix / 64, 256>>>(z, cb);
    quant_kernel<<<PBLOCKS, 256>>>(z, cb, out, total);

    int write_idx = (out_size >= total + npix) ? 1 : 0;
    hist_kernel<<<64, 256>>>(out + total, npix, write_idx);

    if (out_size >= total + npix + 2) {
        finalize_kernel<<<1, 256>>>(out + total + npix, PBLOCKS,
                                    1.0 / (double)total, npix);
    }
    (void)n_in;
}